// round 1
// baseline (speedup 1.0000x reference)
#include <cuda_runtime.h>
#include <math.h>

// Problem dims (fixed by the dataset)
#define BB 4
#define LL 4096
#define DD 1024
#define NN 64
#define NCH 32            // scan chunks per sequence
#define TCH (LL / NCH)    // 128 steps per chunk

typedef unsigned long long ull;

// ---------------- scratch (device globals: no allocation allowed) ----------------
__device__ float g_conv[BB * LL * DD];   // 64 MB causal-conv output
__device__ float g_Bt[BB * LL * NN];     // softplus gate
__device__ float g_Ct[BB * LL * NN];     // tanh gate
__device__ float g_u[BB * LL * NN];      // x @ Ws + bs
__device__ float g_y[BB * LL * NN];      // scan output
__device__ float g_carry[BB * NCH * NN]; // chunk carries

// ---------------- helpers ----------------
__device__ __forceinline__ float sp(float v) {           // softplus, stable
    return v > 20.f ? v : log1pf(expf(v));
}

__device__ __forceinline__ ull pk(float lo, float hi) {
    ull r; asm("mov.b64 %0, {%1, %2};" : "=l"(r) : "f"(lo), "f"(hi)); return r;
}
__device__ __forceinline__ void fma2(ull& d, ull a, ull b) {
    asm("fma.rn.f32x2 %0, %1, %2, %0;" : "+l"(d) : "l"(a), "l"(b));
}
__device__ __forceinline__ float2 upk(ull v) {
    float2 f; asm("mov.b64 {%0, %1}, %2;" : "=f"(f.x), "=f"(f.y) : "l"(v)); return f;
}

__device__ __forceinline__ float4 f4fma(float4 acc, float4 a, float4 b) {
    acc.x = fmaf(a.x, b.x, acc.x);
    acc.y = fmaf(a.y, b.y, acc.y);
    acc.z = fmaf(a.z, b.z, acc.z);
    acc.w = fmaf(a.w, b.w, acc.w);
    return acc;
}

// ---------------- kernel 1: causal depthwise conv (K=4) ----------------
// grid (L/16, B), 256 threads (one per 4-float lane of D)
__global__ void __launch_bounds__(256) conv_kernel(
    const float* __restrict__ x, const float* __restrict__ w,
    const float* __restrict__ cb, float* __restrict__ conv)
{
    const int S = DD / 4;                 // 256 float4 lanes
    const int d4 = threadIdx.x;
    const int b  = blockIdx.y;
    const int l0 = blockIdx.x * 16;

    const float4* X = (const float4*)x + (size_t)b * LL * S + d4;
    float4*       O = (float4*)conv    + (size_t)b * LL * S + d4;
    const float4* W = (const float4*)w;

    float4 w0 = W[0 * S + d4], w1 = W[1 * S + d4];
    float4 w2 = W[2 * S + d4], w3 = W[3 * S + d4];
    float4 cb4 = ((const float4*)cb)[d4];

    float4 z = make_float4(0.f, 0.f, 0.f, 0.f);
    float4 xm3 = (l0 - 3 >= 0) ? X[(size_t)(l0 - 3) * S] : z;
    float4 xm2 = (l0 - 2 >= 0) ? X[(size_t)(l0 - 2) * S] : z;
    float4 xm1 = (l0 - 1 >= 0) ? X[(size_t)(l0 - 1) * S] : z;

#pragma unroll
    for (int t = 0; t < 16; ++t) {
        float4 xc = X[(size_t)(l0 + t) * S];
        float4 o = cb4;
        o = f4fma(o, w0, xm3);
        o = f4fma(o, w1, xm2);
        o = f4fma(o, w2, xm1);
        o = f4fma(o, w3, xc);
        O[(size_t)(l0 + t) * S] = o;
        xm3 = xm2; xm2 = xm1; xm1 = xc;
    }
}

// ---------------- kernel 2: fp32 GEMM, 64x64 tile, BK=16, packed f32x2 FFMA ----
// C[m,n] = sum_k A[m,k]*Bm[k,n] + bias[n], optional activation.
// 128 threads, each computes an 8x4 microtile (stored as 8x2 f32x2 pairs).
// mode: 0 = linear, 1 = softplus, 2 = tanh
__global__ void __launch_bounds__(128) gemm64(
    const float* __restrict__ A, int lda,
    const float* __restrict__ Bm, int ldb,
    const float* __restrict__ bias,
    float* __restrict__ C, int ldc,
    int Ktot, int mode)
{
    __shared__ __align__(16) float As[16][64];
    __shared__ __align__(16) float Bs[16][64];

    const int tid = threadIdx.x;
    const int m0 = blockIdx.x * 64;
    const int n0 = blockIdx.y * 64;

    // global-load mapping
    const int ar = tid >> 2;             // 0..31: A rows ar, ar+32
    const int ac = (tid & 3) * 4;        // k-offset within tile
    const int br = tid >> 4;             // 0..7: B k-rows br, br+8
    const int bc = (tid & 15) * 4;       // col offset

    // compute mapping
    const int tx = tid & 15, ty = tid >> 4;
    const int r0 = ty * 8, c0 = tx * 4;

    const int nt = Ktot / 16;
    const float* Ag0 = A + (size_t)(m0 + ar) * lda + ac;
    const float* Ag1 = A + (size_t)(m0 + ar + 32) * lda + ac;
    const float* Bg0 = Bm + (size_t)br * ldb + n0 + bc;
    const float* Bg1 = Bm + (size_t)(br + 8) * ldb + n0 + bc;

    float4 a0 = *(const float4*)Ag0;
    float4 a1 = *(const float4*)Ag1;
    float4 b0 = *(const float4*)Bg0;
    float4 b1 = *(const float4*)Bg1;

    ull acc[8][2];
#pragma unroll
    for (int i = 0; i < 8; ++i) { acc[i][0] = 0ull; acc[i][1] = 0ull; }

    for (int kt = 0; kt < nt; ++kt) {
        // stage current tile into smem (A transposed: As[k][m])
        As[ac + 0][ar] = a0.x; As[ac + 1][ar] = a0.y;
        As[ac + 2][ar] = a0.z; As[ac + 3][ar] = a0.w;
        As[ac + 0][ar + 32] = a1.x; As[ac + 1][ar + 32] = a1.y;
        As[ac + 2][ar + 32] = a1.z; As[ac + 3][ar + 32] = a1.w;
        *(float4*)&Bs[br][bc]     = b0;
        *(float4*)&Bs[br + 8][bc] = b1;
        __syncthreads();

        if (kt + 1 < nt) {  // prefetch next tile into registers
            a0 = *(const float4*)(Ag0 + (kt + 1) * 16);
            a1 = *(const float4*)(Ag1 + (kt + 1) * 16);
            b0 = *(const float4*)(Bg0 + (size_t)(kt + 1) * 16 * ldb);
            b1 = *(const float4*)(Bg1 + (size_t)(kt + 1) * 16 * ldb);
        }

#pragma unroll
        for (int k = 0; k < 16; ++k) {
            float4 va0 = *(const float4*)&As[k][r0];
            float4 va1 = *(const float4*)&As[k][r0 + 4];
            ull vb01 = *(const ull*)&Bs[k][c0];
            ull vb23 = *(const ull*)&Bs[k][c0 + 2];
            ull d;
            d = pk(va0.x, va0.x); fma2(acc[0][0], d, vb01); fma2(acc[0][1], d, vb23);
            d = pk(va0.y, va0.y); fma2(acc[1][0], d, vb01); fma2(acc[1][1], d, vb23);
            d = pk(va0.z, va0.z); fma2(acc[2][0], d, vb01); fma2(acc[2][1], d, vb23);
            d = pk(va0.w, va0.w); fma2(acc[3][0], d, vb01); fma2(acc[3][1], d, vb23);
            d = pk(va1.x, va1.x); fma2(acc[4][0], d, vb01); fma2(acc[4][1], d, vb23);
            d = pk(va1.y, va1.y); fma2(acc[5][0], d, vb01); fma2(acc[5][1], d, vb23);
            d = pk(va1.z, va1.z); fma2(acc[6][0], d, vb01); fma2(acc[6][1], d, vb23);
            d = pk(va1.w, va1.w); fma2(acc[7][0], d, vb01); fma2(acc[7][1], d, vb23);
        }
        __syncthreads();
    }

    // epilogue
    float4 bb = *(const float4*)&bias[n0 + c0];
#pragma unroll
    for (int i = 0; i < 8; ++i) {
        float2 v0 = upk(acc[i][0]);
        float2 v1 = upk(acc[i][1]);
        float4 o = make_float4(v0.x + bb.x, v0.y + bb.y, v1.x + bb.z, v1.y + bb.w);
        if (mode == 1) {
            o.x = sp(o.x); o.y = sp(o.y); o.z = sp(o.z); o.w = sp(o.w);
        } else if (mode == 2) {
            o.x = tanhf(o.x); o.y = tanhf(o.y); o.z = tanhf(o.z); o.w = tanhf(o.w);
        }
        int row = m0 + r0 + i;
        *(float4*)&C[(size_t)row * ldc + n0 + c0] = o;
    }
}

// ---------------- scan kernels (chunk-parallel linear recurrence) ----------------
// decay[n] is time-invariant, so: local scans -> serial carry combine -> fixup pass.

__global__ void __launch_bounds__(64) scan_partial(
    const float* __restrict__ A_log, const float* __restrict__ dt_log,
    const float* __restrict__ u, const float* __restrict__ Bt,
    float* __restrict__ carry)
{
    const int n = threadIdx.x, ch = blockIdx.x, b = blockIdx.y;
    const float dt = sp(dt_log[n]);
    const float decay = 1.f - dt * sp(A_log[n]);   // 1 + dt*A, A = -softplus(A_log)
    size_t base = ((size_t)b * LL + (size_t)ch * TCH) * NN + n;
    float s = 0.f;
#pragma unroll 4
    for (int t = 0; t < TCH; ++t) {
        float uu = u[base + (size_t)t * NN];
        float bt = Bt[base + (size_t)t * NN];
        s = fmaf(decay, s, (dt * bt) * uu);
    }
    carry[((size_t)b * NCH + ch) * NN + n] = s;
}

__global__ void __launch_bounds__(256) scan_carry(
    const float* __restrict__ A_log, const float* __restrict__ dt_log,
    float* __restrict__ carry)
{
    const int tid = threadIdx.x;
    const int b = tid >> 6, n = tid & 63;
    const float dt = sp(dt_log[n]);
    const float decay = 1.f - dt * sp(A_log[n]);
    float dp = decay;
#pragma unroll
    for (int i = 0; i < 7; ++i) dp *= dp;          // decay^128 (TCH = 2^7)
    float c = 0.f;
    for (int ch = 0; ch < NCH; ++ch) {
        size_t idx = ((size_t)b * NCH + ch) * NN + n;
        float e = carry[idx];
        carry[idx] = c;                             // carry_in for this chunk
        c = fmaf(dp, c, e);
    }
}

__global__ void __launch_bounds__(64) scan_final(
    const float* __restrict__ A_log, const float* __restrict__ dt_log,
    const float* __restrict__ u, const float* __restrict__ Bt,
    const float* __restrict__ Ct, const float* __restrict__ carry,
    float* __restrict__ y)
{
    const int n = threadIdx.x, ch = blockIdx.x, b = blockIdx.y;
    const float dt = sp(dt_log[n]);
    const float decay = 1.f - dt * sp(A_log[n]);
    size_t base = ((size_t)b * LL + (size_t)ch * TCH) * NN + n;
    float s = carry[((size_t)b * NCH + ch) * NN + n];
#pragma unroll 4
    for (int t = 0; t < TCH; ++t) {
        float uu = u[base + (size_t)t * NN];
        float bt = Bt[base + (size_t)t * NN];
        float ct = Ct[base + (size_t)t * NN];
        s = fmaf(decay, s, (dt * bt) * uu);
        y[base + (size_t)t * NN] = ct * s;
    }
}

// ---------------- launch ----------------
extern "C" void kernel_launch(void* const* d_in, const int* in_sizes, int n_in,
                              void* d_out, int out_size)
{
    const float* x      = (const float*)d_in[0];
    const float* conv_w = (const float*)d_in[1];
    const float* conv_b = (const float*)d_in[2];
    const float* Wp     = (const float*)d_in[3];
    const float* bp     = (const float*)d_in[4];
    const float* Ws     = (const float*)d_in[5];
    const float* bs     = (const float*)d_in[6];
    const float* A_log  = (const float*)d_in[7];
    const float* dt_log = (const float*)d_in[8];
    const float* Wo     = (const float*)d_in[9];
    const float* bo     = (const float*)d_in[10];
    float* out = (float*)d_out;

    float *conv_p, *bt_p, *ct_p, *u_p, *y_p, *carry_p;
    cudaGetSymbolAddress((void**)&conv_p,  g_conv);
    cudaGetSymbolAddress((void**)&bt_p,    g_Bt);
    cudaGetSymbolAddress((void**)&ct_p,    g_Ct);
    cudaGetSymbolAddress((void**)&u_p,     g_u);
    cudaGetSymbolAddress((void**)&y_p,     g_y);
    cudaGetSymbolAddress((void**)&carry_p, g_carry);

    const int M = BB * LL;   // 16384

    // 1) causal conv
    conv_kernel<<<dim3(LL / 16, BB), 256>>>(x, conv_w, conv_b, conv_p);

    // 2) proj GEMMs on conv: B_t = softplus(conv@Wp[:, :64] + bp[:64]),
    //                        C_t = tanh(conv@Wp[:, 64:] + bp[64:])
    gemm64<<<dim3(M / 64, 1), 128>>>(conv_p, DD, Wp,      2 * NN, bp,      bt_p, NN, DD, 1);
    gemm64<<<dim3(M / 64, 1), 128>>>(conv_p, DD, Wp + NN, 2 * NN, bp + NN, ct_p, NN, DD, 2);

    // 3) u = x @ Ws + bs
    gemm64<<<dim3(M / 64, 1), 128>>>(x, DD, Ws, NN, bs, u_p, NN, DD, 0);

    // 4) chunk-parallel scan -> y
    scan_partial<<<dim3(NCH, BB), 64>>>(A_log, dt_log, u_p, bt_p, carry_p);
    scan_carry<<<1, 256>>>(A_log, dt_log, carry_p);
    scan_final<<<dim3(NCH, BB), 64>>>(A_log, dt_log, u_p, bt_p, ct_p, carry_p, y_p);

    // 5) out = y @ Wo + bo
    gemm64<<<dim3(M / 64, DD / 64), 128>>>(y_p, NN, Wo, DD, bo, out, DD, NN, 0);
}